// round 15
// baseline (speedup 1.0000x reference)
#include <cuda_runtime.h>
#include <float.h>
#include <math.h>

// Problem constants (fixed shapes from reference setup_inputs)
#define D_DIM   2048
#define SK      64       // sqrt_K
#define NEXPERT 4096     // SK*SK
#define TOPK    8
#define NMAX    8192

typedef unsigned long long ULL;

// Scratch for fused projection S = x @ [W1;W2]^T  -> [N, 128]
__device__ float g_S[NMAX * 2 * SK];

// ---------------------------------------------------------------------------
// packed f32x2 helpers (exact fp32)
// ---------------------------------------------------------------------------
__device__ __forceinline__ ULL pk2(float lo, float hi) {
    ULL r;
    asm("mov.b64 %0, {%1, %2};" : "=l"(r) : "f"(lo), "f"(hi));
    return r;
}
__device__ __forceinline__ void fma2(ULL& d, ULL a, ULL b) {
    asm("fma.rn.f32x2 %0, %1, %2, %0;" : "+l"(d) : "l"(a), "l"(b));
}
__device__ __forceinline__ ULL add2(ULL a, ULL b) {
    ULL r;
    asm("add.rn.f32x2 %0, %1, %2;" : "=l"(r) : "l"(a), "l"(b));
    return r;
}

// ---------------------------------------------------------------------------
// Kernel A: SGEMM  S[N,128] = x[N,2048] @ concat(W1,W2)[128,2048]^T
// Inner loop = R2 verbatim (8 rows/warp, 16 fma2/kk).  CTA shrunk to
// 4 warps / BM=32 -> grid 256, ~2 CTAs/SM co-resident -> 4 warps/SMSP
// (R11 showed 2 warps/SMSP left the fma pipe 66% idle on latency).
// Per-(row,col) accumulation sequential over k — bit-identical numerics.
// ---------------------------------------------------------------------------
#define BM 32
#define BN 128
#define BK 16
#define NIT (D_DIM / BK)

__global__ __launch_bounds__(128) void pkr_gemm(
    const float* __restrict__ x,
    const float* __restrict__ W1,
    const float* __restrict__ W2)
{
    __shared__ float As[2][BK][BM];   // 2 x 2 KB
    __shared__ float Bs[2][BK][BN];   // 2 x 8 KB

    const int tid  = threadIdx.x;
    const int w    = tid >> 5;        // 0..3
    const int lane = tid & 31;
    const int bm0  = blockIdx.x * BM;

    // A loader: row ar (0..31), k offset akc in {0,4,8,12} — 1 job/thread
    const int ar  = tid >> 2;
    const int akc = (tid & 3) * 4;
    const float* xp = x + (size_t)(bm0 + ar) * D_DIM + akc;

    // B loader: 4 jobs/thread; job j -> row (tid&31)+32*(j&1) of W1 (j<2)
    // or W2 (j>=2), k offset bkc = (tid>>5)*4; Bs col = j*32 + (tid&31)
    const int brow = tid & 31;
    const int bkc  = (tid >> 5) * 4;
    const float* wp[4];
    wp[0] = W1 + (size_t)(brow)      * D_DIM + bkc;
    wp[1] = W1 + (size_t)(brow + 32) * D_DIM + bkc;
    wp[2] = W2 + (size_t)(brow)      * D_DIM + bkc;
    wp[3] = W2 + (size_t)(brow + 32) * D_DIM + bkc;

    ULL acc[8][2];
    #pragma unroll
    for (int i = 0; i < 8; i++) { acc[i][0] = 0ULL; acc[i][1] = 0ULL; }

    // stage 0 fill
    {
        float4 a = *(const float4*)xp;
        As[0][akc + 0][ar] = a.x;  As[0][akc + 1][ar] = a.y;
        As[0][akc + 2][ar] = a.z;  As[0][akc + 3][ar] = a.w;
        #pragma unroll
        for (int m = 0; m < 4; m++) {
            float4 b = *(const float4*)wp[m];
            const int col = m * 32 + brow;
            Bs[0][bkc + 0][col] = b.x; Bs[0][bkc + 1][col] = b.y;
            Bs[0][bkc + 2][col] = b.z; Bs[0][bkc + 3][col] = b.w;
        }
    }
    __syncthreads();

    int p = 0;
    float4 a_pf, b_pf[4];
    for (int it = 0; it < NIT; ++it) {
        const bool has_next = (it + 1) < NIT;
        if (has_next) {
            const int k0 = (it + 1) * BK;
            a_pf = *(const float4*)(xp + k0);
            #pragma unroll
            for (int m = 0; m < 4; m++)
                b_pf[m] = *(const float4*)(wp[m] + k0);
        }

        // ---- inner loop: identical shape to R2 (8 rows x 4 cols / thread) ----
        #pragma unroll
        for (int kk = 0; kk < BK; kk++) {
            float4 a01 = *(const float4*)&As[p][kk][w * 8];
            float4 a23 = *(const float4*)&As[p][kk][w * 8 + 4];
            ulonglong2 bb = *(const ulonglong2*)&Bs[p][kk][lane * 4];
            float av[8] = {a01.x, a01.y, a01.z, a01.w,
                           a23.x, a23.y, a23.z, a23.w};
            #pragma unroll
            for (int i = 0; i < 8; i++) {
                ULL ad = pk2(av[i], av[i]);
                fma2(acc[i][0], ad, bb.x);
                fma2(acc[i][1], ad, bb.y);
            }
        }

        if (has_next) {
            const int q = p ^ 1;
            As[q][akc + 0][ar] = a_pf.x;  As[q][akc + 1][ar] = a_pf.y;
            As[q][akc + 2][ar] = a_pf.z;  As[q][akc + 3][ar] = a_pf.w;
            #pragma unroll
            for (int m = 0; m < 4; m++) {
                const int col = m * 32 + brow;
                Bs[q][bkc + 0][col] = b_pf[m].x; Bs[q][bkc + 1][col] = b_pf[m].y;
                Bs[q][bkc + 2][col] = b_pf[m].z; Bs[q][bkc + 3][col] = b_pf[m].w;
            }
            __syncthreads();
            p = q;
        }
    }

    // warp w owns rows bm0 + w*8 .. +7; lane owns cols lane*4..+3
    #pragma unroll
    for (int i = 0; i < 8; i++) {
        const size_t row = (size_t)(bm0 + w * 8 + i);
        ulonglong2 v; v.x = acc[i][0]; v.y = acc[i][1];
        *(ulonglong2*)&g_S[row * (2 * SK) + lane * 4] = v;
    }
}

// ---------------------------------------------------------------------------
// Kernel B (R9 structure + packed-f32x2 stream): one warp per row; score
// stream interleaved into the s1/s2 argmax rounds; stable tie-breaks.
// Packed adds are bit-identical IEEE fp32 adds.
// ---------------------------------------------------------------------------
__global__ __launch_bounds__(256) void pkr_topk(
    float* __restrict__ idx_out,
    float* __restrict__ probs_out,
    float* __restrict__ scores_out)
{
    __shared__ float sb[8][2 * SK];
    __shared__ float c1v[8][8], c2v[8][8];
    __shared__ int   c1i[8][8], c2i[8][8];

    const int w    = threadIdx.x >> 5;
    const int lane = threadIdx.x & 31;
    const size_t row = (size_t)blockIdx.x * 8 + w;

    *(float4*)&sb[w][lane * 4] =
        *(const float4*)&g_S[row * (2 * SK) + lane * 4];
    __syncwarp();

    // --- stream setup (packed s2 pairs) ---
    const int j = (lane & 15) * 4;
    const float4 s2q = *(const float4*)&sb[w][SK + j];
    const ULL s2p0 = pk2(s2q.x, s2q.y);
    const ULL s2p1 = pk2(s2q.z, s2q.w);
    const int ihalf = lane >> 4;
    // per-iter stride: i advances by 2 rows = 2*SK floats
    float* __restrict__ sptr =
        scores_out ? scores_out + row * NEXPERT + (size_t)ihalf * SK + j
                   : (float*)0;

    // --- topk state ---
    float a0 = sb[w][lane],      a1 = sb[w][lane + 32];
    int   i0 = lane,             i1 = lane + 32;
    float b0 = sb[w][SK + lane], b1 = sb[w][SK + lane + 32];
    int   j0 = lane,             j1 = lane + 32;

    #pragma unroll
    for (int r = 0; r < TOPK; r++) {
        // ---- 4 interleaved stream iterations ----
        if (sptr) {
            #pragma unroll
            for (int u = 0; u < 4; u++) {
                const int t = r * 4 + u;
                const ULL s1d = pk2(sb[w][t * 2 + ihalf], sb[w][t * 2 + ihalf]);
                ulonglong2 v;
                v.x = add2(s1d, s2p0);
                v.y = add2(s1d, s2p1);
                __stcs((ulonglong2*)(sptr + (size_t)t * 2 * SK), v);
            }
        }
        // ---- s1 round r ----
        {
            float v; int i;
            if (a0 > a1 || (a0 == a1 && i0 < i1)) { v = a0; i = i0; }
            else                                  { v = a1; i = i1; }
            #pragma unroll
            for (int off = 16; off; off >>= 1) {
                float ov = __shfl_xor_sync(0xffffffffu, v, off);
                int   oi = __shfl_xor_sync(0xffffffffu, i, off);
                if (ov > v || (ov == v && oi < i)) { v = ov; i = oi; }
            }
            if (lane == r) { c1v[w][r] = v; c1i[w][r] = i; }
            if (i == i0) { a0 = -FLT_MAX; i0 = 1 << 30; }
            if (i == i1) { a1 = -FLT_MAX; i1 = 1 << 30; }
        }
        // ---- s2 round r ----
        {
            float u; int jj;
            if (b0 > b1 || (b0 == b1 && j0 < j1)) { u = b0; jj = j0; }
            else                                  { u = b1; jj = j1; }
            #pragma unroll
            for (int off = 16; off; off >>= 1) {
                float ou = __shfl_xor_sync(0xffffffffu, u, off);
                int   oj = __shfl_xor_sync(0xffffffffu, jj, off);
                if (ou > u || (ou == u && oj < jj)) { u = ou; jj = oj; }
            }
            if (lane == r) { c2v[w][r] = u; c2i[w][r] = jj; }
            if (jj == j0) { b0 = -FLT_MAX; j0 = 1 << 30; }
            if (jj == j1) { b1 = -FLT_MAX; j1 = 1 << 30; }
        }
    }
    __syncwarp();

    // ---- top-8 of the 64 candidate pairs (2 per lane) ----
    const int p0 = lane, p1 = lane + 32;
    float cv0 = c1v[w][p0 >> 3] + c2v[w][p0 & 7];
    int   ci0 = c1i[w][p0 >> 3] * SK + c2i[w][p0 & 7];
    float cv1 = c1v[w][p1 >> 3] + c2v[w][p1 & 7];
    int   ci1 = c1i[w][p1 >> 3] * SK + c2i[w][p1 & 7];

    float mv[TOPK];
    int   mi[TOPK];
    #pragma unroll
    for (int r = 0; r < TOPK; r++) {
        float v; int i;
        if (cv0 > cv1 || (cv0 == cv1 && ci0 < ci1)) { v = cv0; i = ci0; }
        else                                        { v = cv1; i = ci1; }
        #pragma unroll
        for (int off = 16; off; off >>= 1) {
            float ov = __shfl_xor_sync(0xffffffffu, v, off);
            int   oi = __shfl_xor_sync(0xffffffffu, i, off);
            if (ov > v || (ov == v && oi < i)) { v = ov; i = oi; }
        }
        mv[r] = v; mi[r] = i;
        if (i == ci0) { cv0 = -FLT_MAX; ci0 = 1 << 30; }
        if (i == ci1) { cv1 = -FLT_MAX; ci1 = 1 << 30; }
    }

    if (lane == 0) {
        float m = mv[0], sum = 0.f, e[TOPK];
        #pragma unroll
        for (int r = 0; r < TOPK; r++) { e[r] = expf(mv[r] - m); sum += e[r]; }
        float inv = 1.f / sum;
        #pragma unroll
        for (int r = 0; r < TOPK; r++) {
            if (idx_out)   idx_out[row * TOPK + r]   = (float)mi[r];
            if (probs_out) probs_out[row * TOPK + r] = e[r] * inv;
        }
    }
}

// ---------------------------------------------------------------------------
extern "C" void kernel_launch(void* const* d_in, const int* in_sizes, int n_in,
                              void* d_out, int out_size) {
    const float* x  = (const float*)d_in[0];
    const float* W1 = (const float*)d_in[1];
    const float* W2 = (const float*)d_in[2];
    (void)n_in;

    int N = in_sizes[0] / D_DIM;   // 8192
    float* out = (float*)d_out;

    float* idxp = 0;
    float* probp = 0;
    float* scorep = 0;
    long long full = (long long)N * (2 * TOPK + NEXPERT);
    if ((long long)out_size == full) {
        idxp   = out;
        probp  = out + (long long)N * TOPK;
        scorep = out + (long long)N * 2 * TOPK;
    } else if ((long long)out_size == (long long)N * NEXPERT) {
        scorep = out;
    } else if ((long long)out_size == (long long)N * 2 * TOPK) {
        idxp  = out;
        probp = out + (long long)N * TOPK;
    } else {
        idxp   = out;
        probp  = out + (long long)N * TOPK;
        scorep = out + (long long)N * 2 * TOPK;
    }

    pkr_gemm<<<N / BM, 128>>>(x, W1, W2);
    pkr_topk<<<N / 8, 256>>>(idxp, probp, scorep);
}

// round 16
// speedup vs baseline: 1.1874x; 1.1874x over previous
#include <cuda_runtime.h>
#include <float.h>
#include <math.h>

// Problem constants (fixed shapes from reference setup_inputs)
#define D_DIM   2048
#define SK      64       // sqrt_K
#define NEXPERT 4096     // SK*SK
#define TOPK    8
#define NMAX    8192

typedef unsigned long long ULL;

// Scratch for fused projection S = x @ [W1;W2]^T  -> [N, 128]
__device__ float g_S[NMAX * 2 * SK];

// ---------------------------------------------------------------------------
// packed f32x2 helpers (exact fp32)
// ---------------------------------------------------------------------------
__device__ __forceinline__ ULL pk2(float lo, float hi) {
    ULL r;
    asm("mov.b64 %0, {%1, %2};" : "=l"(r) : "f"(lo), "f"(hi));
    return r;
}
__device__ __forceinline__ void fma2(ULL& d, ULL a, ULL b) {
    asm("fma.rn.f32x2 %0, %1, %2, %0;" : "+l"(d) : "l"(a), "l"(b));
}

// ---------------------------------------------------------------------------
// Kernel A: R2's SGEMM with BK=32 (inner kk-body and thread mapping
// UNCHANGED; only stage length doubled -> 64 barriers instead of 128).
// S[N,128] = x[N,2048] @ concat(W1,W2)[128,2048]^T
// BM=64 x BN=128, 256 threads, double-buffered smem (48 KB).
// Per-(row,col) accumulation sequential over k — bit-identical numerics.
// ---------------------------------------------------------------------------
#define BM 64
#define BN 128
#define BK 32
#define NIT (D_DIM / BK)   // 64

__global__ __launch_bounds__(256) void pkr_gemm(
    const float* __restrict__ x,
    const float* __restrict__ W1,
    const float* __restrict__ W2)
{
    __shared__ float As[2][BK][BM];   // 2 x 8 KB
    __shared__ float Bs[2][BK][BN];   // 2 x 16 KB

    const int tid  = threadIdx.x;
    const int w    = tid >> 5;
    const int lane = tid & 31;
    const int bm0  = blockIdx.x * BM;

    // A loader: 2 jobs/thread.  job j: idx = tid + 256j ->
    //   row = idx>>3 (0..63), k offset = (idx&7)*4
    const int ar  = tid >> 3;             // rows for job0 / job1: ar, ar+32
    const int akc = (tid & 7) * 4;
    const float* xpa = x + (size_t)(bm0 + ar)      * D_DIM + akc;
    const float* xpb = x + (size_t)(bm0 + ar + 32) * D_DIM + akc;

    // B loader: 4 jobs/thread.  job j: idx = tid + 256j ->
    //   col = idx>>3 (0..127), k offset = (idx&7)*4
    // cols: ar, ar+32, ar+64, ar+96  (first two from W1, last two from W2)
    const float* wp[4];
    wp[0] = W1 + (size_t)(ar)      * D_DIM + akc;
    wp[1] = W1 + (size_t)(ar + 32) * D_DIM + akc;
    wp[2] = W2 + (size_t)(ar)      * D_DIM + akc;
    wp[3] = W2 + (size_t)(ar + 32) * D_DIM + akc;
    const int bcol[4] = {ar, ar + 32, ar + 64, ar + 96};

    ULL acc[8][2];
    #pragma unroll
    for (int i = 0; i < 8; i++) { acc[i][0] = 0ULL; acc[i][1] = 0ULL; }

    // stage 0 fill
    {
        float4 a0 = *(const float4*)xpa;
        float4 a1 = *(const float4*)xpb;
        #pragma unroll
        for (int i = 0; i < 4; i++) {
            As[0][akc + i][ar]      = ((const float*)&a0)[i];
            As[0][akc + i][ar + 32] = ((const float*)&a1)[i];
        }
        #pragma unroll
        for (int m = 0; m < 4; m++) {
            float4 b = *(const float4*)wp[m];
            #pragma unroll
            for (int i = 0; i < 4; i++)
                Bs[0][akc + i][bcol[m]] = ((const float*)&b)[i];
        }
    }
    __syncthreads();

    int p = 0;
    float4 a0_pf, a1_pf, b_pf[4];
    for (int it = 0; it < NIT; ++it) {
        const bool has_next = (it + 1) < NIT;
        if (has_next) {
            const int k0 = (it + 1) * BK;
            a0_pf = *(const float4*)(xpa + k0);
            a1_pf = *(const float4*)(xpb + k0);
            #pragma unroll
            for (int m = 0; m < 4; m++)
                b_pf[m] = *(const float4*)(wp[m] + k0);
        }

        // ---- inner loop: byte-identical body to R2, 32 kk per stage ----
        #pragma unroll
        for (int kk = 0; kk < BK; kk++) {
            float4 a01 = *(const float4*)&As[p][kk][w * 8];
            float4 a23 = *(const float4*)&As[p][kk][w * 8 + 4];
            ulonglong2 bb = *(const ulonglong2*)&Bs[p][kk][lane * 4];
            float av[8] = {a01.x, a01.y, a01.z, a01.w,
                           a23.x, a23.y, a23.z, a23.w};
            #pragma unroll
            for (int i = 0; i < 8; i++) {
                ULL ad = pk2(av[i], av[i]);
                fma2(acc[i][0], ad, bb.x);
                fma2(acc[i][1], ad, bb.y);
            }
        }

        if (has_next) {
            const int q = p ^ 1;
            #pragma unroll
            for (int i = 0; i < 4; i++) {
                As[q][akc + i][ar]      = ((const float*)&a0_pf)[i];
                As[q][akc + i][ar + 32] = ((const float*)&a1_pf)[i];
            }
            #pragma unroll
            for (int m = 0; m < 4; m++)
                #pragma unroll
                for (int i = 0; i < 4; i++)
                    Bs[q][akc + i][bcol[m]] = ((const float*)&b_pf[m])[i];
            __syncthreads();
            p = q;
        }
    }

    #pragma unroll
    for (int i = 0; i < 8; i++) {
        const size_t row = (size_t)(bm0 + w * 8 + i);
        ulonglong2 v; v.x = acc[i][0]; v.y = acc[i][1];
        *(ulonglong2*)&g_S[row * (2 * SK) + lane * 4] = v;
    }
}

// ---------------------------------------------------------------------------
// Kernel B (R9 verbatim — best measured, 24.7us): one warp per row; score
// stream interleaved into the s1/s2 argmax rounds; stable tie-breaks.
// ---------------------------------------------------------------------------
__global__ __launch_bounds__(256) void pkr_topk(
    float* __restrict__ idx_out,
    float* __restrict__ probs_out,
    float* __restrict__ scores_out)
{
    __shared__ float sb[8][2 * SK];
    __shared__ float c1v[8][8], c2v[8][8];
    __shared__ int   c1i[8][8], c2i[8][8];

    const int w    = threadIdx.x >> 5;
    const int lane = threadIdx.x & 31;
    const size_t row = (size_t)blockIdx.x * 8 + w;

    *(float4*)&sb[w][lane * 4] =
        *(const float4*)&g_S[row * (2 * SK) + lane * 4];
    __syncwarp();

    float* __restrict__ srow =
        scores_out ? scores_out + row * NEXPERT : (float*)0;
    const int j = (lane & 15) * 4;
    const float4 s2q = *(const float4*)&sb[w][SK + j];
    const int ihalf = lane >> 4;

    float a0 = sb[w][lane],      a1 = sb[w][lane + 32];
    int   i0 = lane,             i1 = lane + 32;
    float b0 = sb[w][SK + lane], b1 = sb[w][SK + lane + 32];
    int   j0 = lane,             j1 = lane + 32;

    #pragma unroll
    for (int r = 0; r < TOPK; r++) {
        if (srow) {
            #pragma unroll
            for (int u = 0; u < 4; u++) {
                const int t = r * 4 + u;
                const int i = t * 2 + ihalf;
                const float s1 = sb[w][i];
                float4 v4;
                v4.x = s1 + s2q.x; v4.y = s1 + s2q.y;
                v4.z = s1 + s2q.z; v4.w = s1 + s2q.w;
                __stcs((float4*)&srow[i * SK + j], v4);
            }
        }
        {
            float v; int i;
            if (a0 > a1 || (a0 == a1 && i0 < i1)) { v = a0; i = i0; }
            else                                  { v = a1; i = i1; }
            #pragma unroll
            for (int off = 16; off; off >>= 1) {
                float ov = __shfl_xor_sync(0xffffffffu, v, off);
                int   oi = __shfl_xor_sync(0xffffffffu, i, off);
                if (ov > v || (ov == v && oi < i)) { v = ov; i = oi; }
            }
            if (lane == r) { c1v[w][r] = v; c1i[w][r] = i; }
            if (i == i0) { a0 = -FLT_MAX; i0 = 1 << 30; }
            if (i == i1) { a1 = -FLT_MAX; i1 = 1 << 30; }
        }
        {
            float u; int jj;
            if (b0 > b1 || (b0 == b1 && j0 < j1)) { u = b0; jj = j0; }
            else                                  { u = b1; jj = j1; }
            #pragma unroll
            for (int off = 16; off; off >>= 1) {
                float ou = __shfl_xor_sync(0xffffffffu, u, off);
                int   oj = __shfl_xor_sync(0xffffffffu, jj, off);
                if (ou > u || (ou == u && oj < jj)) { u = ou; jj = oj; }
            }
            if (lane == r) { c2v[w][r] = u; c2i[w][r] = jj; }
            if (jj == j0) { b0 = -FLT_MAX; j0 = 1 << 30; }
            if (jj == j1) { b1 = -FLT_MAX; j1 = 1 << 30; }
        }
    }
    __syncwarp();

    const int p0 = lane, p1 = lane + 32;
    float cv0 = c1v[w][p0 >> 3] + c2v[w][p0 & 7];
    int   ci0 = c1i[w][p0 >> 3] * SK + c2i[w][p0 & 7];
    float cv1 = c1v[w][p1 >> 3] + c2v[w][p1 & 7];
    int   ci1 = c1i[w][p1 >> 3] * SK + c2i[w][p1 & 7];

    float mv[TOPK];
    int   mi[TOPK];
    #pragma unroll
    for (int r = 0; r < TOPK; r++) {
        float v; int i;
        if (cv0 > cv1 || (cv0 == cv1 && ci0 < ci1)) { v = cv0; i = ci0; }
        else                                        { v = cv1; i = ci1; }
        #pragma unroll
        for (int off = 16; off; off >>= 1) {
            float ov = __shfl_xor_sync(0xffffffffu, v, off);
            int   oi = __shfl_xor_sync(0xffffffffu, i, off);
            if (ov > v || (ov == v && oi < i)) { v = ov; i = oi; }
        }
        mv[r] = v; mi[r] = i;
        if (i == ci0) { cv0 = -FLT_MAX; ci0 = 1 << 30; }
        if (i == ci1) { cv1 = -FLT_MAX; ci1 = 1 << 30; }
    }

    if (lane == 0) {
        float m = mv[0], sum = 0.f, e[TOPK];
        #pragma unroll
        for (int r = 0; r < TOPK; r++) { e[r] = expf(mv[r] - m); sum += e[r]; }
        float inv = 1.f / sum;
        #pragma unroll
        for (int r = 0; r < TOPK; r++) {
            if (idx_out)   idx_out[row * TOPK + r]   = (float)mi[r];
            if (probs_out) probs_out[row * TOPK + r] = e[r] * inv;
        }
    }
}

// ---------------------------------------------------------------------------
extern "C" void kernel_launch(void* const* d_in, const int* in_sizes, int n_in,
                              void* d_out, int out_size) {
    const float* x  = (const float*)d_in[0];
    const float* W1 = (const float*)d_in[1];
    const float* W2 = (const float*)d_in[2];
    (void)n_in;

    int N = in_sizes[0] / D_DIM;   // 8192
    float* out = (float*)d_out;

    float* idxp = 0;
    float* probp = 0;
    float* scorep = 0;
    long long full = (long long)N * (2 * TOPK + NEXPERT);
    if ((long long)out_size == full) {
        idxp   = out;
        probp  = out + (long long)N * TOPK;
        scorep = out + (long long)N * 2 * TOPK;
    } else if ((long long)out_size == (long long)N * NEXPERT) {
        scorep = out;
    } else if ((long long)out_size == (long long)N * 2 * TOPK) {
        idxp  = out;
        probp = out + (long long)N * TOPK;
    } else {
        idxp   = out;
        probp  = out + (long long)N * TOPK;
        scorep = out + (long long)N * 2 * TOPK;
    }

    pkr_gemm<<<N / BM, 256>>>(x, W1, W2);
    pkr_topk<<<N / 8, 256>>>(idxp, probp, scorep);
}

// round 17
// speedup vs baseline: 1.3425x; 1.1306x over previous
#include <cuda_runtime.h>
#include <float.h>
#include <math.h>

// Problem constants (fixed shapes from reference setup_inputs)
#define D_DIM   2048
#define SK      64       // sqrt_K
#define NEXPERT 4096     // SK*SK
#define TOPK    8
#define NMAX    8192

typedef unsigned long long ULL;

// Scratch for fused projection S = x @ [W1;W2]^T  -> [N, 128]
__device__ float g_S[NMAX * 2 * SK];

// ---------------------------------------------------------------------------
// packed f32x2 helpers (exact fp32)
// ---------------------------------------------------------------------------
__device__ __forceinline__ ULL pk2(float lo, float hi) {
    ULL r;
    asm("mov.b64 %0, {%1, %2};" : "=l"(r) : "f"(lo), "f"(hi));
    return r;
}
__device__ __forceinline__ void fma2(ULL& d, ULL a, ULL b) {
    asm("fma.rn.f32x2 %0, %1, %2, %0;" : "+l"(d) : "l"(a), "l"(b));
}

// ---------------------------------------------------------------------------
// Kernel A (R2 verbatim — measured 140us; empirical optimum over 9 variants):
// SGEMM  S[N,128] = x[N,2048] @ concat(W1,W2)[128,2048]^T
// BM=64 x BN=128, BK=16, 256 threads, double-buffered smem.
// Thread tile: 8 rows x 4 cols.  Warp covers 8 rows x all 128 cols.
// ---------------------------------------------------------------------------
#define BM 64
#define BN 128
#define BK 16
#define NIT (D_DIM / BK)

__global__ __launch_bounds__(256) void pkr_gemm(
    const float* __restrict__ x,
    const float* __restrict__ W1,
    const float* __restrict__ W2)
{
    __shared__ float As[2][BK][BM];   // 2 x 4 KB
    __shared__ float Bs[2][BK][BN];   // 2 x 8 KB

    const int tid  = threadIdx.x;
    const int w    = tid >> 5;
    const int lane = tid & 31;
    const int bm0  = blockIdx.x * BM;

    const int ar  = tid >> 2;
    const int akc = (tid & 3) * 4;
    const float* xp = x + (size_t)(bm0 + ar) * D_DIM + akc;

    const int bc  = tid & 63;
    const int bkc = (tid >> 6) * 4;
    const float* w1p = W1 + (size_t)bc * D_DIM + bkc;
    const float* w2p = W2 + (size_t)bc * D_DIM + bkc;

    ULL acc[8][2];
    #pragma unroll
    for (int i = 0; i < 8; i++) { acc[i][0] = 0ULL; acc[i][1] = 0ULL; }

    {
        float4 a  = *(const float4*)xp;
        float4 b1 = *(const float4*)w1p;
        float4 b2 = *(const float4*)w2p;
        As[0][akc + 0][ar] = a.x;  As[0][akc + 1][ar] = a.y;
        As[0][akc + 2][ar] = a.z;  As[0][akc + 3][ar] = a.w;
        Bs[0][bkc + 0][bc] = b1.x; Bs[0][bkc + 1][bc] = b1.y;
        Bs[0][bkc + 2][bc] = b1.z; Bs[0][bkc + 3][bc] = b1.w;
        Bs[0][bkc + 0][bc + SK] = b2.x; Bs[0][bkc + 1][bc + SK] = b2.y;
        Bs[0][bkc + 2][bc + SK] = b2.z; Bs[0][bkc + 3][bc + SK] = b2.w;
    }
    __syncthreads();

    int p = 0;
    float4 a_pf, b1_pf, b2_pf;
    for (int it = 0; it < NIT; ++it) {
        const bool has_next = (it + 1) < NIT;
        if (has_next) {
            const int k0 = (it + 1) * BK;
            a_pf  = *(const float4*)(xp  + k0);
            b1_pf = *(const float4*)(w1p + k0);
            b2_pf = *(const float4*)(w2p + k0);
        }

        #pragma unroll
        for (int kk = 0; kk < BK; kk++) {
            float4 a01 = *(const float4*)&As[p][kk][w * 8];
            float4 a23 = *(const float4*)&As[p][kk][w * 8 + 4];
            ulonglong2 bb = *(const ulonglong2*)&Bs[p][kk][lane * 4];
            float av[8] = {a01.x, a01.y, a01.z, a01.w,
                           a23.x, a23.y, a23.z, a23.w};
            #pragma unroll
            for (int i = 0; i < 8; i++) {
                ULL ad = pk2(av[i], av[i]);
                fma2(acc[i][0], ad, bb.x);
                fma2(acc[i][1], ad, bb.y);
            }
        }

        if (has_next) {
            const int q = p ^ 1;
            As[q][akc + 0][ar] = a_pf.x;  As[q][akc + 1][ar] = a_pf.y;
            As[q][akc + 2][ar] = a_pf.z;  As[q][akc + 3][ar] = a_pf.w;
            Bs[q][bkc + 0][bc] = b1_pf.x; Bs[q][bkc + 1][bc] = b1_pf.y;
            Bs[q][bkc + 2][bc] = b1_pf.z; Bs[q][bkc + 3][bc] = b1_pf.w;
            Bs[q][bkc + 0][bc + SK] = b2_pf.x; Bs[q][bkc + 1][bc + SK] = b2_pf.y;
            Bs[q][bkc + 2][bc + SK] = b2_pf.z; Bs[q][bkc + 3][bc + SK] = b2_pf.w;
            __syncthreads();
            p = q;
        }
    }

    #pragma unroll
    for (int i = 0; i < 8; i++) {
        const size_t row = (size_t)(bm0 + w * 8 + i);
        ulonglong2 v; v.x = acc[i][0]; v.y = acc[i][1];
        *(ulonglong2*)&g_S[row * (2 * SK) + lane * 4] = v;
    }
}

// ---------------------------------------------------------------------------
// Kernel B (R9 verbatim — measured 24.7us): one warp per row; score stream
// interleaved into the s1/s2 argmax rounds (LSU/DRAM work hides under the
// shfl chains); decomposed top-8 (top8(s1) x top8(s2) -> 64 candidates);
// stable lower-index tie-breaks matching jax.lax.top_k.
// ---------------------------------------------------------------------------
__global__ __launch_bounds__(256) void pkr_topk(
    float* __restrict__ idx_out,
    float* __restrict__ probs_out,
    float* __restrict__ scores_out)
{
    __shared__ float sb[8][2 * SK];
    __shared__ float c1v[8][8], c2v[8][8];
    __shared__ int   c1i[8][8], c2i[8][8];

    const int w    = threadIdx.x >> 5;
    const int lane = threadIdx.x & 31;
    const size_t row = (size_t)blockIdx.x * 8 + w;

    *(float4*)&sb[w][lane * 4] =
        *(const float4*)&g_S[row * (2 * SK) + lane * 4];
    __syncwarp();

    float* __restrict__ srow =
        scores_out ? scores_out + row * NEXPERT : (float*)0;
    const int j = (lane & 15) * 4;
    const float4 s2q = *(const float4*)&sb[w][SK + j];
    const int ihalf = lane >> 4;

    float a0 = sb[w][lane],      a1 = sb[w][lane + 32];
    int   i0 = lane,             i1 = lane + 32;
    float b0 = sb[w][SK + lane], b1 = sb[w][SK + lane + 32];
    int   j0 = lane,             j1 = lane + 32;

    #pragma unroll
    for (int r = 0; r < TOPK; r++) {
        if (srow) {
            #pragma unroll
            for (int u = 0; u < 4; u++) {
                const int t = r * 4 + u;
                const int i = t * 2 + ihalf;
                const float s1 = sb[w][i];
                float4 v4;
                v4.x = s1 + s2q.x; v4.y = s1 + s2q.y;
                v4.z = s1 + s2q.z; v4.w = s1 + s2q.w;
                __stcs((float4*)&srow[i * SK + j], v4);
            }
        }
        {
            float v; int i;
            if (a0 > a1 || (a0 == a1 && i0 < i1)) { v = a0; i = i0; }
            else                                  { v = a1; i = i1; }
            #pragma unroll
            for (int off = 16; off; off >>= 1) {
                float ov = __shfl_xor_sync(0xffffffffu, v, off);
                int   oi = __shfl_xor_sync(0xffffffffu, i, off);
                if (ov > v || (ov == v && oi < i)) { v = ov; i = oi; }
            }
            if (lane == r) { c1v[w][r] = v; c1i[w][r] = i; }
            if (i == i0) { a0 = -FLT_MAX; i0 = 1 << 30; }
            if (i == i1) { a1 = -FLT_MAX; i1 = 1 << 30; }
        }
        {
            float u; int jj;
            if (b0 > b1 || (b0 == b1 && j0 < j1)) { u = b0; jj = j0; }
            else                                  { u = b1; jj = j1; }
            #pragma unroll
            for (int off = 16; off; off >>= 1) {
                float ou = __shfl_xor_sync(0xffffffffu, u, off);
                int   oj = __shfl_xor_sync(0xffffffffu, jj, off);
                if (ou > u || (ou == u && oj < jj)) { u = ou; jj = oj; }
            }
            if (lane == r) { c2v[w][r] = u; c2i[w][r] = jj; }
            if (jj == j0) { b0 = -FLT_MAX; j0 = 1 << 30; }
            if (jj == j1) { b1 = -FLT_MAX; j1 = 1 << 30; }
        }
    }
    __syncwarp();

    const int p0 = lane, p1 = lane + 32;
    float cv0 = c1v[w][p0 >> 3] + c2v[w][p0 & 7];
    int   ci0 = c1i[w][p0 >> 3] * SK + c2i[w][p0 & 7];
    float cv1 = c1v[w][p1 >> 3] + c2v[w][p1 & 7];
    int   ci1 = c1i[w][p1 >> 3] * SK + c2i[w][p1 & 7];

    float mv[TOPK];
    int   mi[TOPK];
    #pragma unroll
    for (int r = 0; r < TOPK; r++) {
        float v; int i;
        if (cv0 > cv1 || (cv0 == cv1 && ci0 < ci1)) { v = cv0; i = ci0; }
        else                                        { v = cv1; i = ci1; }
        #pragma unroll
        for (int off = 16; off; off >>= 1) {
            float ov = __shfl_xor_sync(0xffffffffu, v, off);
            int   oi = __shfl_xor_sync(0xffffffffu, i, off);
            if (ov > v || (ov == v && oi < i)) { v = ov; i = oi; }
        }
        mv[r] = v; mi[r] = i;
        if (i == ci0) { cv0 = -FLT_MAX; ci0 = 1 << 30; }
        if (i == ci1) { cv1 = -FLT_MAX; ci1 = 1 << 30; }
    }

    if (lane == 0) {
        float m = mv[0], sum = 0.f, e[TOPK];
        #pragma unroll
        for (int r = 0; r < TOPK; r++) { e[r] = expf(mv[r] - m); sum += e[r]; }
        float inv = 1.f / sum;
        #pragma unroll
        for (int r = 0; r < TOPK; r++) {
            if (idx_out)   idx_out[row * TOPK + r]   = (float)mi[r];
            if (probs_out) probs_out[row * TOPK + r] = e[r] * inv;
        }
    }
}

// ---------------------------------------------------------------------------
extern "C" void kernel_launch(void* const* d_in, const int* in_sizes, int n_in,
                              void* d_out, int out_size) {
    const float* x  = (const float*)d_in[0];
    const float* W1 = (const float*)d_in[1];
    const float* W2 = (const float*)d_in[2];
    (void)n_in;

    int N = in_sizes[0] / D_DIM;   // 8192
    float* out = (float*)d_out;

    float* idxp = 0;
    float* probp = 0;
    float* scorep = 0;
    long long full = (long long)N * (2 * TOPK + NEXPERT);
    if ((long long)out_size == full) {
        idxp   = out;
        probp  = out + (long long)N * TOPK;
        scorep = out + (long long)N * 2 * TOPK;
    } else if ((long long)out_size == (long long)N * NEXPERT) {
        scorep = out;
    } else if ((long long)out_size == (long long)N * 2 * TOPK) {
        idxp  = out;
        probp = out + (long long)N * TOPK;
    } else {
        idxp   = out;
        probp  = out + (long long)N * TOPK;
        scorep = out + (long long)N * 2 * TOPK;
    }

    // Harmless carveout hint (attribute set is not a capture op; no allocs).
    cudaFuncSetAttribute(pkr_gemm,
                         cudaFuncAttributePreferredSharedMemoryCarveout, 50);

    pkr_gemm<<<N / BM, 256>>>(x, W1, W2);
    pkr_topk<<<N / 8, 256>>>(idxp, probp, scorep);
}